// round 3
// baseline (speedup 1.0000x reference)
#include <cuda_runtime.h>
#include <cstdint>

// Problem constants (fixed by the dataset)
#define NWORDS 100000
#define SHEADS 64
#define QB     50
#define PB     3
#define TILE   256
#define GRID   ((NWORDS + TILE - 1) / TILE)   // 391

typedef unsigned long long ull;

// ---- packed f32x2 ops (sm_103a; ptxas never emits FFMA2 from C++) ----
#define FMA2(d,a,b,c) asm("fma.rn.f32x2 %0, %1, %2, %3;" : "=l"(d) : "l"(a), "l"(b), "l"(c))
#define MUL2(d,a,b)   asm("mul.rn.f32x2 %0, %1, %2;"     : "=l"(d) : "l"(a), "l"(b))
#define PACK2(d,lo,hi)   asm("mov.b64 %0, {%1, %2};" : "=l"(d) : "f"(lo), "f"(hi))
#define UNPACK2(lo,hi,s) asm("mov.b64 {%0, %1}, %2;" : "=f"(lo), "=f"(hi) : "l"(s))

// Scratch (no cudaMalloc allowed): preprocessed heads (pair-interleaved) + hr + partials
// layout: g_heads[(q*32 + spair)*8 + 2*p + (s&1)]  (6 used of 8 floats per entry),
//         then hr[64] appended at offset 12800.
__device__ __align__(16) float  g_heads[QB * 32 * 8 + SHEADS];  // 12864 floats
__device__ double g_part[GRID];

__device__ __forceinline__ float softplus20(float x) {
    float z = 20.0f * x;
    return (z > 20.0f) ? z : log1pf(expf(z));
}

// ---------------- kernel 1: preprocess heads + head ratios ----------------
__global__ void prep_kernel(const float* __restrict__ heads_param,
                            const float* __restrict__ hr_param) {
    int tid = threadIdx.x;
    // heads: softplus(20x), L1-normalize over p, scatter into pair-interleaved layout
    for (int i = tid; i < SHEADS * QB; i += blockDim.x) {
        int s = i / QB;
        int q = i - s * QB;
        const float* hp = heads_param + (s * QB + q) * PB;
        float a = softplus20(hp[0]);
        float b = softplus20(hp[1]);
        float c = softplus20(hp[2]);
        float sum = fmaxf(a + b + c, 1e-12f);
        int base = (q * 32 + (s >> 1)) * 8 + (s & 1);
        g_heads[base + 0] = a / sum;
        g_heads[base + 2] = b / sum;
        g_heads[base + 4] = c / sum;
        g_heads[base + 6] = 0.0f;  // pad
    }
    // head ratios (tiny; one thread, deterministic)
    if (tid == 0) {
        float sp[SHEADS];
        float sum = 0.0f;
        for (int s = 0; s < SHEADS; ++s) { sp[s] = softplus20(hr_param[s]); sum += sp[s]; }
        sum = fmaxf(sum, 1e-12f);
        const float add = 0.001f / (float)SHEADS;
        for (int s = 0; s < SHEADS; ++s)
            g_heads[QB * 32 * 8 + s] = (sp[s] / sum + add) / 1.001f;
    }
}

// ---------------- kernel 2: main coverage + loss ----------------
__global__ void __launch_bounds__(TILE, 1)
main_kernel(const float* __restrict__ pauli,   // [N, Q, P] = [N,150]
            const float* __restrict__ coeff) { // [N]
    extern __shared__ float sm[];
    float* sm_pauli = sm;                         // TILE*150 floats (153600 B)
    float* sm_heads = sm + TILE * 150;            // 12800 floats  (51200 B)
    float* sm_hr    = sm_heads + QB * 32 * 8;     // 64 floats
    __shared__ float warpsum[8];

    const int tid  = threadIdx.x;
    const int base = blockIdx.x * TILE;
    const int rows = min(TILE, NWORDS - base);

    // cooperative load: heads + hr (12864 floats, 16B aligned)
    {
        const float4* src = (const float4*)g_heads;
        float4*       dst = (float4*)sm_heads;
        #pragma unroll 4
        for (int i = tid; i < (QB * 32 * 8 + SHEADS) / 4; i += TILE) dst[i] = src[i];
    }
    // cooperative load: pauli tile. base*600 bytes is 16B aligned (base mult of 256);
    // rows is always even (256 or 160) -> rows*150 divisible by 4.
    {
        const float4* src = (const float4*)(pauli + (size_t)base * 150);
        float4*       dst = (float4*)sm_pauli;
        const int n4 = rows * 150 / 4;
        for (int i = tid; i < n4; i += TILE) dst[i] = src[i];
    }
    __syncthreads();

    const float* row = sm_pauli + ((tid < rows) ? tid : 0) * 150;

    ull acc[32];
    ull one; PACK2(one, 1.0f, 1.0f);
    #pragma unroll
    for (int i = 0; i < 32; ++i) acc[i] = one;

    for (int q = 0; q < QB; ++q) {
        const float p0 = row[q * 3 + 0];
        const float p1 = row[q * 3 + 1];
        const float p2 = row[q * 3 + 2];
        ull p0x, p1x, p2x;
        PACK2(p0x, p0, p0); PACK2(p1x, p1, p1); PACK2(p2x, p2, p2);
        const ull* hp = (const ull*)(sm_heads + q * 32 * 8);
        #pragma unroll
        for (int i = 0; i < 32; ++i) {
            ull h0 = hp[i * 4 + 0];   // (h0[s_even], h0[s_odd])  -> LDS.128 pair
            ull h1 = hp[i * 4 + 1];
            ull h2 = hp[i * 4 + 2];   // -> LDS.64
            ull d;
            MUL2(d, p2x, h2);
            FMA2(d, p1x, h1, d);
            FMA2(d, p0x, h0, d);
            MUL2(acc[i], acc[i], d);
        }
    }

    // ratio-weighted sum over heads (packed), then horizontal add
    const ull* hrp = (const ull*)sm_hr;
    ull zero; PACK2(zero, 0.0f, 0.0f);
    ull w2 = zero;
    #pragma unroll
    for (int i = 0; i < 32; ++i) FMA2(w2, hrp[i], acc[i], w2);
    float wlo, whi; UNPACK2(wlo, whi, w2);
    const float w = wlo + whi;

    float term = 0.0f;
    if (tid < rows) {
        const float c = coeff[base + tid];
        term = (c * c) / w;
    }

    // deterministic block reduction -> per-block partial (no float atomics)
    #pragma unroll
    for (int off = 16; off; off >>= 1)
        term += __shfl_down_sync(0xffffffffu, term, off);
    if ((tid & 31) == 0) warpsum[tid >> 5] = term;
    __syncthreads();
    if (tid == 0) {
        double v = 0.0;
        #pragma unroll
        for (int wsi = 0; wsi < 8; ++wsi) v += (double)warpsum[wsi];
        g_part[blockIdx.x] = v;
    }
}

// ---------------- kernel 3: deterministic final reduction ----------------
__global__ void finish_kernel(float* __restrict__ out) {
    __shared__ double red[256];
    int t = threadIdx.x;
    double v = 0.0;
    if (t < GRID)        v += g_part[t];
    if (t + 256 < GRID)  v += g_part[t + 256];
    red[t] = v;
    __syncthreads();
    #pragma unroll
    for (int off = 128; off; off >>= 1) {
        if (t < off) red[t] += red[t + off];
        __syncthreads();
    }
    if (t == 0) out[0] = (float)red[0];
}

extern "C" void kernel_launch(void* const* d_in, const int* in_sizes, int n_in,
                              void* d_out, int out_size) {
    const float* pauli = (const float*)d_in[0];  // [N,Q,P]
    const float* coeff = (const float*)d_in[1];  // [N]
    const float* hp    = (const float*)d_in[2];  // [S,Q,P]
    const float* hrp   = (const float*)d_in[3];  // [S]
    float* out = (float*)d_out;

    const size_t smem = (size_t)(TILE * 150 + QB * 32 * 8 + SHEADS) * sizeof(float); // 205 KB
    cudaFuncSetAttribute(main_kernel, cudaFuncAttributeMaxDynamicSharedMemorySize, (int)smem);

    prep_kernel<<<1, 256>>>(hp, hrp);
    main_kernel<<<GRID, TILE, smem>>>(pauli, coeff);
    finish_kernel<<<1, 256>>>(out);
}

// round 4
// speedup vs baseline: 1.6906x; 1.6906x over previous
#include <cuda_runtime.h>
#include <cstdint>

// Problem constants (fixed by the dataset)
#define NWORDS 100000
#define SHEADS 64
#define QB     50
#define PB     3
#define TILE   256
#define GRID   ((NWORDS + TILE - 1) / TILE)   // 391

typedef unsigned long long ull;

// ---- packed f32x2 ops (sm_103a; ptxas never emits FFMA2 from C++) ----
#define FMA2(d,a,b,c) asm("fma.rn.f32x2 %0, %1, %2, %3;" : "=l"(d) : "l"(a), "l"(b), "l"(c))
#define MUL2(d,a,b)   asm("mul.rn.f32x2 %0, %1, %2;"     : "=l"(d) : "l"(a), "l"(b))
#define PACK2(d,lo,hi)   asm("mov.b64 %0, {%1, %2};" : "=l"(d) : "f"(lo), "f"(hi))
#define UNPACK2(lo,hi,s) asm("mov.b64 {%0, %1}, %2;" : "=f"(lo), "=f"(hi) : "l"(s))

__device__ double g_part[GRID];

// Branch-free softplus(20x): max(z,0) + log1p(exp(-|z|)).
// log1pf keeps full accuracy for tiny exp(-|z|) (vs __logf(1+u) which would
// flush tiny terms to 0 and zero out small heads before normalization).
__device__ __forceinline__ float softplus20(float x) {
    float z = 20.0f * x;
    return fmaxf(z, 0.0f) + log1pf(__expf(-fabsf(z)));
}

// ---------------- kernel 1: fused prep + coverage + loss ----------------
// Dynamic smem layout (floats):
//   sm_pauli : TILE*150            = 38400   (153600 B)
//   sm_h0    : QB*64               =  3200   (ull pairs, SoA)
//   sm_h1    : QB*64               =  3200
//   sm_h2    : QB*64               =  3200
//   sm_hr    : 64                  (32 ull pairs)
// total = 48064 floats = 192256 B  (< 227 KB, 1 CTA/SM)
__global__ void __launch_bounds__(TILE, 1)
main_kernel(const float* __restrict__ pauli,        // [N, Q, P] = [N,150]
            const float* __restrict__ coeff,        // [N]
            const float* __restrict__ heads_param,  // [S, Q, P]
            const float* __restrict__ hr_param) {   // [S]
    extern __shared__ float sm[];
    float* sm_pauli = sm;                        // 38400
    float* sm_h0    = sm + TILE * 150;           // 3200
    float* sm_h1    = sm_h0 + QB * 64;           // 3200
    float* sm_h2    = sm_h1 + QB * 64;           // 3200
    float* sm_hr    = sm_h2 + QB * 64;           // 64
    __shared__ float warpsum[8];
    __shared__ float s_hrtmp[64];
    __shared__ float s_hrsum;

    const int tid  = threadIdx.x;
    const int base = blockIdx.x * TILE;
    const int rows = min(TILE, NWORDS - base);

    // ---- cooperative load: pauli tile (coalesced float4) ----
    // base*600 bytes is 16B aligned (base multiple of 256); rows*150 div by 4
    // (rows is 256 or 160).
    {
        const float4* src = (const float4*)(pauli + (size_t)base * 150);
        float4*       dst = (float4*)sm_pauli;
        const int n4 = rows * 150 / 4;
        for (int i = tid; i < n4; i += TILE) dst[i] = src[i];
    }

    // ---- per-block head preprocessing (replaces the old serial prep kernel) ----
    // heads: softplus(20x), L1-normalize over p, scatter into SoA pair layout:
    //   sm_hX[q*64 + (s>>1)*2 + (s&1)]  -> ull index [q*32 + pair]
    for (int i = tid; i < SHEADS * QB; i += TILE) {
        const int s = i / QB;
        const int q = i - s * QB;
        const float* hp = heads_param + i * 3;   // i == s*QB + q
        float a = softplus20(hp[0]);
        float b = softplus20(hp[1]);
        float c = softplus20(hp[2]);
        float inv = 1.0f / fmaxf(a + b + c, 1e-12f);
        const int idx = q * 64 + (s >> 1) * 2 + (s & 1);
        sm_h0[idx] = a * inv;
        sm_h1[idx] = b * inv;
        sm_h2[idx] = c * inv;
    }

    // head ratios: parallel softplus + deterministic shfl-tree reduce
    if (tid < SHEADS) s_hrtmp[tid] = softplus20(hr_param[tid]);
    __syncthreads();
    if (tid < 32) {
        float v = s_hrtmp[tid] + s_hrtmp[tid + 32];
        #pragma unroll
        for (int off = 16; off; off >>= 1)
            v += __shfl_down_sync(0xffffffffu, v, off);
        if (tid == 0) s_hrsum = fmaxf(v, 1e-12f);
    }
    __syncthreads();
    if (tid < SHEADS)
        sm_hr[tid] = (s_hrtmp[tid] / s_hrsum + 0.001f / (float)SHEADS) / 1.001f;
    __syncthreads();

    // ---- main coverage loop: thread = word, 32 packed head-pairs ----
    const float* row = sm_pauli + ((tid < rows) ? tid : 0) * 150;

    ull acc[32];
    ull one; PACK2(one, 1.0f, 1.0f);
    #pragma unroll
    for (int i = 0; i < 32; ++i) acc[i] = one;

    for (int q = 0; q < QB; ++q) {
        const float p0 = row[q * 3 + 0];
        const float p1 = row[q * 3 + 1];
        const float p2 = row[q * 3 + 2];
        ull p0x, p1x, p2x;
        PACK2(p0x, p0, p0); PACK2(p1x, p1, p1); PACK2(p2x, p2, p2);
        // SoA head arrays for this q: load 2 pairs per LDS.128 (broadcast,
        // conflict-free) -> 1.5 LDS per inner iter instead of 2.
        const ulonglong2* H0 = (const ulonglong2*)(sm_h0 + q * 64);
        const ulonglong2* H1 = (const ulonglong2*)(sm_h1 + q * 64);
        const ulonglong2* H2 = (const ulonglong2*)(sm_h2 + q * 64);
        #pragma unroll
        for (int j = 0; j < 16; ++j) {
            ulonglong2 a0 = H0[j];
            ulonglong2 a1 = H1[j];
            ulonglong2 a2 = H2[j];
            ull d0, d1;
            MUL2(d0, p2x, a2.x);
            FMA2(d0, p1x, a1.x, d0);
            FMA2(d0, p0x, a0.x, d0);
            MUL2(acc[2 * j + 0], acc[2 * j + 0], d0);
            MUL2(d1, p2x, a2.y);
            FMA2(d1, p1x, a1.y, d1);
            FMA2(d1, p0x, a0.y, d1);
            MUL2(acc[2 * j + 1], acc[2 * j + 1], d1);
        }
    }

    // ratio-weighted sum over heads (packed), then horizontal add
    const ull* hrp = (const ull*)sm_hr;
    ull w2; PACK2(w2, 0.0f, 0.0f);
    #pragma unroll
    for (int i = 0; i < 32; ++i) FMA2(w2, hrp[i], acc[i], w2);
    float wlo, whi; UNPACK2(wlo, whi, w2);
    const float w = wlo + whi;

    float term = 0.0f;
    if (tid < rows) {
        const float c = coeff[base + tid];
        term = (c * c) / w;
    }

    // deterministic block reduction -> per-block partial (no float atomics)
    #pragma unroll
    for (int off = 16; off; off >>= 1)
        term += __shfl_down_sync(0xffffffffu, term, off);
    if ((tid & 31) == 0) warpsum[tid >> 5] = term;
    __syncthreads();
    if (tid == 0) {
        double v = 0.0;
        #pragma unroll
        for (int wsi = 0; wsi < 8; ++wsi) v += (double)warpsum[wsi];
        g_part[blockIdx.x] = v;
    }
}

// ---------------- kernel 2: deterministic final reduction ----------------
__global__ void finish_kernel(float* __restrict__ out) {
    __shared__ double red[256];
    int t = threadIdx.x;
    double v = 0.0;
    if (t < GRID)        v += g_part[t];
    if (t + 256 < GRID)  v += g_part[t + 256];
    red[t] = v;
    __syncthreads();
    #pragma unroll
    for (int off = 128; off; off >>= 1) {
        if (t < off) red[t] += red[t + off];
        __syncthreads();
    }
    if (t == 0) out[0] = (float)red[0];
}

extern "C" void kernel_launch(void* const* d_in, const int* in_sizes, int n_in,
                              void* d_out, int out_size) {
    const float* pauli = (const float*)d_in[0];  // [N,Q,P]
    const float* coeff = (const float*)d_in[1];  // [N]
    const float* hp    = (const float*)d_in[2];  // [S,Q,P]
    const float* hrp   = (const float*)d_in[3];  // [S]
    float* out = (float*)d_out;

    const size_t smem = (size_t)(TILE * 150 + 3 * QB * 64 + SHEADS) * sizeof(float); // 192256 B
    cudaFuncSetAttribute(main_kernel, cudaFuncAttributeMaxDynamicSharedMemorySize, (int)smem);

    main_kernel<<<GRID, TILE, smem>>>(pauli, coeff, hp, hrp);
    finish_kernel<<<1, 256>>>(out);
}

// round 6
// speedup vs baseline: 1.8069x; 1.0688x over previous
#include <cuda_runtime.h>
#include <cstdint>

// Problem constants (fixed by the dataset)
#define NWORDS 100000
#define SHEADS 64
#define QB     50
#define TILE   128
#define NTILES ((NWORDS + TILE - 1) / TILE)   // 782 (last tile: 32 rows)
#define GRIDX  152
#define NTHR   256

typedef unsigned long long ull;

// ---- packed f32x2 ops (sm_103a; ptxas never emits FFMA2 from C++) ----
#define FMA2(d,a,b,c) asm("fma.rn.f32x2 %0, %1, %2, %3;" : "=l"(d) : "l"(a), "l"(b), "l"(c))
#define MUL2(d,a,b)   asm("mul.rn.f32x2 %0, %1, %2;"     : "=l"(d) : "l"(a), "l"(b))
#define PACK2(d,lo,hi)   asm("mov.b64 %0, {%1, %2};" : "=l"(d) : "f"(lo), "f"(hi))
#define UNPACK2(lo,hi,s) asm("mov.b64 {%0, %1}, %2;" : "=f"(lo), "=f"(hi) : "l"(s))

__device__ double g_part[NTILES];
__device__ int    g_ticket = GRIDX;   // reset by finish_kernel after every run

// 16B async copy, L1-bypass (no reuse of pauli data)
__device__ __forceinline__ void cp_async16(float* smem_dst, const float* gsrc) {
    uint32_t s = (uint32_t)__cvta_generic_to_shared(smem_dst);
    asm volatile("cp.async.cg.shared.global [%0], [%1], 16;" :: "r"(s), "l"(gsrc));
}
__device__ __forceinline__ void cp_commit()   { asm volatile("cp.async.commit_group;"); }
__device__ __forceinline__ void cp_wait_all() { asm volatile("cp.async.wait_all;"); }

// Branch-free softplus(20x): max(z,0) + log1p(exp(-|z|)); log1pf keeps accuracy
// for tiny exp(-|z|) so small heads survive normalization.
__device__ __forceinline__ float softplus20(float x) {
    float z = 20.0f * x;
    return fmaxf(z, 0.0f) + log1pf(__expf(-fabsf(z)));
}

// Dynamic smem layout (floats):
//   buf0   : TILE*150 = 19200
//   buf1   : TILE*150 = 19200
//   sm_h0  : QB*64    =  3200   (SoA per-p head arrays, pair-interleaved)
//   sm_h1  : QB*64    =  3200
//   sm_h2  : QB*64    =  3200
//   sm_hr  : 64
//   sm_w   : TILE = 128        (cross-half coverage combine)
// total = 48192 floats = 192768 B  (< 227 KB -> 1 CTA/SM)
#define SMEM_FLOATS (2*TILE*150 + 3*QB*64 + SHEADS + TILE)

__global__ void __launch_bounds__(NTHR, 1)
main_kernel(const float* __restrict__ pauli,        // [N,150]
            const float* __restrict__ coeff,        // [N]
            const float* __restrict__ heads_param,  // [S,Q,3]
            const float* __restrict__ hr_param) {   // [S]
    extern __shared__ float sm[];
    float* buf[2];
    buf[0]       = sm;
    buf[1]       = sm + TILE * 150;
    float* sm_h0 = sm + 2 * TILE * 150;
    float* sm_h1 = sm_h0 + QB * 64;
    float* sm_h2 = sm_h1 + QB * 64;
    float* sm_hr = sm_h2 + QB * 64;
    float* sm_w  = sm_hr + SHEADS;
    __shared__ float warpsum[4];
    __shared__ float s_hrtmp[SHEADS];
    __shared__ float s_hrsum;
    __shared__ int   s_nxt;          // block-uniform next ticket

    const int tid  = threadIdx.x;
    const int half = tid >> 7;     // 0: heads 0-31, 1: heads 32-63
    const int word = tid & 127;

    // ---- kick off prefetch of this block's first tile ----
    int cur = blockIdx.x;          // GRIDX <= NTILES, always valid here
    {
        const int rows = min(TILE, NWORDS - cur * TILE);
        const int n16  = rows * 150 / 4;              // rows multiple of 32
        const float* src = pauli + (size_t)cur * TILE * 150;
        for (int i = tid; i < n16; i += NTHR)
            cp_async16(buf[0] + i * 4, src + i * 4);
        cp_commit();
    }

    // ---- head prep, once per block, overlapped with the cp.async in flight ----
    for (int i = tid; i < SHEADS * QB; i += NTHR) {
        const int s = i / QB;
        const int q = i - s * QB;
        const float* hp = heads_param + i * 3;        // i == s*QB + q
        float a = softplus20(hp[0]);
        float b = softplus20(hp[1]);
        float c = softplus20(hp[2]);
        float inv = 1.0f / fmaxf(a + b + c, 1e-12f);
        const int idx = q * 64 + (s >> 1) * 2 + (s & 1);
        sm_h0[idx] = a * inv;
        sm_h1[idx] = b * inv;
        sm_h2[idx] = c * inv;
    }
    if (tid < SHEADS) s_hrtmp[tid] = softplus20(hr_param[tid]);
    __syncthreads();
    if (tid < 32) {
        float v = s_hrtmp[tid] + s_hrtmp[tid + 32];
        #pragma unroll
        for (int off = 16; off; off >>= 1)
            v += __shfl_down_sync(0xffffffffu, v, off);
        if (tid == 0) s_hrsum = fmaxf(v, 1e-12f);
    }
    __syncthreads();
    if (tid < SHEADS)
        sm_hr[tid] = (s_hrtmp[tid] / s_hrsum + 0.001f / (float)SHEADS) / 1.001f;

    // ---- BLOCK-UNIFORM ticket fetch (R5 bug: this was per-thread) ----
    if (tid == 0) s_nxt = atomicAdd(&g_ticket, 1);

    int pb = 0;                    // buffer holding `cur`
    cp_wait_all();
    __syncthreads();               // first tile + heads + hr + s_nxt ready

    while (cur < NTILES) {
        const int nxt = s_nxt;     // uniform: written before the barrier above
                                   // (or before B2 of the previous iteration)

        // ---- prefetch the next tile into the other buffer ----
        if (nxt < NTILES) {
            const int rows_n = min(TILE, NWORDS - nxt * TILE);
            const int n16    = rows_n * 150 / 4;
            const float* src = pauli + (size_t)nxt * TILE * 150;
            float* dst = buf[pb ^ 1];
            for (int i = tid; i < n16; i += NTHR)
                cp_async16(dst + i * 4, src + i * 4);
        }
        cp_commit();

        // ---- coverage: this thread = (word, 16 head-pairs of its half) ----
        const int rows = min(TILE, NWORDS - cur * TILE);
        const float* row = buf[pb] + ((word < rows) ? word : 0) * 150;

        ull acc[16];
        ull one; PACK2(one, 1.0f, 1.0f);
        #pragma unroll
        for (int i = 0; i < 16; ++i) acc[i] = one;

        for (int q = 0; q < QB; ++q) {
            const float p0 = row[q * 3 + 0];
            const float p1 = row[q * 3 + 1];
            const float p2 = row[q * 3 + 2];
            ull p0x, p1x, p2x;
            PACK2(p0x, p0, p0); PACK2(p1x, p1, p1); PACK2(p2x, p2, p2);
            const ulonglong2* H0 = (const ulonglong2*)sm_h0 + q * 16 + half * 8;
            const ulonglong2* H1 = (const ulonglong2*)sm_h1 + q * 16 + half * 8;
            const ulonglong2* H2 = (const ulonglong2*)sm_h2 + q * 16 + half * 8;
            #pragma unroll
            for (int j = 0; j < 8; ++j) {
                ulonglong2 a0 = H0[j];   // broadcast LDS.128, conflict-free
                ulonglong2 a1 = H1[j];
                ulonglong2 a2 = H2[j];
                ull d0, d1;
                MUL2(d0, p2x, a2.x);
                FMA2(d0, p1x, a1.x, d0);
                FMA2(d0, p0x, a0.x, d0);
                MUL2(acc[2 * j + 0], acc[2 * j + 0], d0);
                MUL2(d1, p2x, a2.y);
                FMA2(d1, p1x, a1.y, d1);
                FMA2(d1, p0x, a0.y, d1);
                MUL2(acc[2 * j + 1], acc[2 * j + 1], d1);
            }
        }

        // ---- ratio-weighted sum over this half's heads ----
        const ull* hrp = (const ull*)sm_hr + half * 16;
        ull w2; PACK2(w2, 0.0f, 0.0f);
        #pragma unroll
        for (int i = 0; i < 16; ++i) FMA2(w2, hrp[i], acc[i], w2);
        float wlo, whi; UNPACK2(wlo, whi, w2);
        const float wh = wlo + whi;

        if (half) sm_w[word] = wh;
        __syncthreads();                 // B1: also separates the s_nxt read
                                         // above from the refill below

        // refill the ticket for the NEXT iteration (after B1: every thread
        // has already read s_nxt; next read happens after B2)
        if (tid == 0 && nxt < NTILES) s_nxt = atomicAdd(&g_ticket, 1);

        float term = 0.0f;
        if (half == 0 && word < rows) {
            const float c = coeff[cur * TILE + word];
            term = (c * c) / (wh + sm_w[word]);
        }
        // deterministic reduction: warps 0-3 hold all nonzero terms
        #pragma unroll
        for (int off = 16; off; off >>= 1)
            term += __shfl_down_sync(0xffffffffu, term, off);
        if (tid < 128 && (tid & 31) == 0) warpsum[tid >> 5] = term;
        __syncthreads();
        if (tid == 0) {
            double v = 0.0;
            #pragma unroll
            for (int wsi = 0; wsi < 4; ++wsi) v += (double)warpsum[wsi];
            g_part[cur] = v;
        }

        // ---- next buffer ready; barrier also protects sm_w/warpsum/s_nxt ----
        cp_wait_all();
        __syncthreads();                 // B2
        cur = nxt;
        pb ^= 1;
    }
}

// ---------------- deterministic final reduction + ticket reset ----------------
__global__ void finish_kernel(float* __restrict__ out) {
    __shared__ double red[256];
    int t = threadIdx.x;
    double v = 0.0;
    #pragma unroll
    for (int k = 0; k < (NTILES + 255) / 256; ++k) {
        int idx = t + k * 256;
        if (idx < NTILES) v += g_part[idx];
    }
    red[t] = v;
    __syncthreads();
    #pragma unroll
    for (int off = 128; off; off >>= 1) {
        if (t < off) red[t] += red[t + off];
        __syncthreads();
    }
    if (t == 0) {
        out[0] = (float)red[0];
        g_ticket = GRIDX;     // reset scheduler for the next replay
    }
}

extern "C" void kernel_launch(void* const* d_in, const int* in_sizes, int n_in,
                              void* d_out, int out_size) {
    const float* pauli = (const float*)d_in[0];  // [N,Q,P]
    const float* coeff = (const float*)d_in[1];  // [N]
    const float* hp    = (const float*)d_in[2];  // [S,Q,P]
    const float* hrp   = (const float*)d_in[3];  // [S]
    float* out = (float*)d_out;

    const size_t smem = (size_t)SMEM_FLOATS * sizeof(float); // 192768 B
    cudaFuncSetAttribute(main_kernel, cudaFuncAttributeMaxDynamicSharedMemorySize, (int)smem);

    main_kernel<<<GRIDX, NTHR, smem>>>(pauli, coeff, hp, hrp);
    finish_kernel<<<1, 256>>>(out);
}